// round 4
// baseline (speedup 1.0000x reference)
#include <cuda_runtime.h>
#include <cstdint>

#define N_ANCH 102000
#define ROWLEN 85
#define CONF 0.25f
#define IOUT 0.45f
#define TOPK 8192
#define KW 128            // 8192/64 words per mask row
#define MAXDET 300
#define CAP 16384
#define NBIN 65536

typedef unsigned long long u64;
typedef unsigned int u32;

// ---------------- static device scratch ----------------
__device__ u64 g_keys[N_ANCH];
__device__ u32 g_cls[N_ANCH];
__device__ u32 g_hist[NBIN];
__device__ u32 g_binoff[NBIN];
__device__ u32 g_bincnt[NBIN];
__device__ int g_thrbin;
__device__ u64 g_slot[CAP];
__device__ float4 g_boxes[TOPK];
__device__ float g_scores[TOPK];
__device__ float g_classes[TOPK];
__device__ u64 g_validm[KW];
__device__ u64 g_mask[(size_t)TOPK * KW];   // 8 MB

// ---------------- K0: zero per-call state ----------------
__global__ void k_init() {
    int t = blockIdx.x * blockDim.x + threadIdx.x;   // 65536 threads
    g_hist[t] = 0u;
    g_bincnt[t] = 0u;
    if (t < CAP) g_slot[t] = 0ULL;
    if (t < KW) g_validm[t] = 0ULL;
    if (t == 0) g_thrbin = 0;
}

// ---------------- K1: score/class + key + 16-bit histogram ----------------
__global__ void k_score(const float* __restrict__ preds) {
    int warp = (blockIdx.x * blockDim.x + threadIdx.x) >> 5;
    int lane = threadIdx.x & 31;
    if (warp >= N_ANCH) return;
    const float* p = preds + (size_t)warp * ROWLEN;
    float e0 = p[lane];
    float obj = __shfl_sync(0xffffffffu, e0, 4);
    u32 sb = 0; int bc = 0;
    if (obj > CONF) {
        float e1 = p[lane + 32];
        float e2 = (lane < 21) ? p[lane + 64] : 0.0f;
        float bv = -1.0f;
        if (lane >= 5) { bv = e0 * obj; bc = lane - 5; }
        float v1 = e1 * obj;
        if (v1 > bv) { bv = v1; bc = lane + 27; }
        if (lane < 21) { float v2 = e2 * obj; if (v2 > bv) { bv = v2; bc = lane + 59; } }
        u32 vb = __float_as_uint(bv);
        u32 m = __reduce_max_sync(0xffffffffu, vb);
        u32 cm = __reduce_min_sync(0xffffffffu, (vb == m) ? (u32)bc : 0xFFFFu);
        sb = m; bc = (int)cm;
    }
    if (lane == 0) {
        g_keys[warp] = ((u64)sb << 32) | (u64)(0xFFFFFFFFu - (u32)warp);
        g_cls[warp] = (u32)bc;
        if (sb) atomicAdd(&g_hist[sb >> 16], 1u);
    }
}

// ---------------- K2: threshold bin + per-bin descending exclusive offsets ----------------
__global__ void k_thresh() {
    __shared__ u32 part[1024];
    int t = threadIdx.x;
    u32 s = 0;
    #pragma unroll
    for (int b = 0; b < 64; b++) s += g_hist[t * 64 + b];
    part[t] = s;
    __syncthreads();
    for (int off = 1; off < 1024; off <<= 1) {   // inclusive suffix sum of chunks
        u32 v = part[t] + ((t + off < 1024) ? part[t + off] : 0u);
        __syncthreads();
        part[t] = v;
        __syncthreads();
    }
    u32 sufNext = (t < 1023) ? part[t + 1] : 0u;
    if (part[t] >= TOPK && sufNext < TOPK) {
        u32 acc = sufNext;
        for (int b = 63; b >= 0; b--) {
            acc += g_hist[t * 64 + b];
            if (acc >= TOPK) { g_thrbin = t * 64 + b; break; }
        }
    }
    if (t == 0 && part[0] < TOPK) g_thrbin = 0;
    // binoff[bin] = #items in bins strictly above bin
    u32 acc = sufNext;
    for (int b = 63; b >= 0; b--) {
        g_binoff[t * 64 + b] = acc;
        acc += g_hist[t * 64 + b];
    }
}

// ---------------- K3: place candidates into bin regions ----------------
__global__ void k_place() {
    int i = blockIdx.x * blockDim.x + threadIdx.x;
    if (i >= N_ANCH) return;
    u64 k = g_keys[i];
    u32 sb = (u32)(k >> 32);
    if (!sb) return;
    int bin = (int)(sb >> 16);
    if (bin < g_thrbin) return;
    u32 p = g_binoff[bin] + atomicAdd(&g_bincnt[bin], 1u);
    if (p < CAP) g_slot[p] = k;
}

// ---------------- K4: within-bin rank + direct gather/write ----------------
__global__ void k_sortbins(const float* __restrict__ preds) {
    int p = blockIdx.x * blockDim.x + threadIdx.x;
    if (p >= CAP) return;
    u64 k = g_slot[p];
    if (!k) return;
    int bin = (int)(k >> 48);
    u32 off = g_binoff[bin];
    u32 cnt = g_bincnt[bin];
    u32 end = off + cnt; if (end > CAP) end = CAP;
    u32 r = off;
    for (u32 q = off; q < end; q++) r += (g_slot[q] > k) ? 1u : 0u;
    if (r >= TOPK) return;
    u32 idx = 0xFFFFFFFFu - (u32)k;
    float s = __uint_as_float((u32)(k >> 32));
    const float* pr = preds + (size_t)idx * ROWLEN;
    float x = pr[0], y = pr[1], w = pr[2], h = pr[3];
    float4 b;
    b.x = y - h * 0.5f;
    b.y = x - w * 0.5f;
    b.z = y + h * 0.5f;
    b.w = x + w * 0.5f;
    g_boxes[r] = b;
    g_scores[r] = s;
    g_classes[r] = (float)g_cls[idx];
    atomicOr(&g_validm[r >> 6], 1ULL << (r & 63));
}

// ---------------- K5: full IoU bitmask (upper-triangular 64x64 tiles) ----------------
__global__ void k_mask() {
    int cy = blockIdx.y, cx = blockIdx.x;
    if (cx < cy) return;
    int t = threadIdx.x;  // 64
    __shared__ float4 sb4[64];
    __shared__ float sa[64];
    float4 jb = g_boxes[cx * 64 + t];
    sb4[t] = jb;
    sa[t] = (jb.z - jb.x) * (jb.w - jb.y);
    float4 ib = g_boxes[cy * 64 + t];
    float ai = (ib.z - ib.x) * (ib.w - ib.y);
    __syncthreads();
    u64 bits = 0;
    int jstart = (cx == cy) ? t + 1 : 0;
    for (int j = jstart; j < 64; j++) {
        float4 b2 = sb4[j];
        float ty = fmaxf(ib.x, b2.x);
        float tx = fmaxf(ib.y, b2.y);
        float by = fminf(ib.z, b2.z);
        float bx = fminf(ib.w, b2.w);
        float inter = fmaxf(by - ty, 0.0f) * fmaxf(bx - tx, 0.0f);
        float uni = ai + sa[j] - inter;
        float iou = inter / (uni + 1e-9f);
        if (iou > IOUT) bits |= (1ULL << j);
    }
    g_mask[(size_t)(cy * 64 + t) * KW + cx] = bits;
}

// ---------------- K6: 8-way batched greedy scan (1 warp) + output ----------------
__global__ void k_scan(float* __restrict__ out) {
    __shared__ int sKept[MAXDET];
    __shared__ int sNk;
    int t = threadIdx.x;    // 128 threads; warp 0 scans
    if (t < 32) {
        int lane = t;
        u64 av[4];
        #pragma unroll
        for (int j = 0; j < 4; j++) av[j] = g_validm[lane * 4 + j];
        int nk = 0;
        while (nk < MAXDET) {
            // lowest nonzero word across 128 words
            int lw = 128;
            #pragma unroll
            for (int j = 3; j >= 0; j--) if (av[j]) lw = lane * 4 + j;
            lw = (int)__reduce_min_sync(0xffffffffu, (u32)lw);
            if (lw == 128) break;
            int owner = lw >> 2, sub = lw & 3;
            u64 aw = __shfl_sync(0xffffffffu, av[sub], owner);
            // extract up to 8 lowest set bits
            int b[8]; int m = 0; u64 rem = aw;
            #pragma unroll
            for (int q = 0; q < 8; q++) {
                if (rem) { b[q] = __ffsll((long long)rem) - 1; rem &= rem - 1; m = q + 1; }
                else b[q] = 0;
            }
            u64 examined = aw ^ rem;
            // fetch rows for all m candidates (each lane: its 4 words)
            u64 r[8][4];
            #pragma unroll
            for (int q = 0; q < 8; q++) {
                if (q < m) {
                    const u64* rp = &g_mask[(size_t)((lw << 6) + b[q]) * KW + lane * 4];
                    r[q][0] = rp[0]; r[q][1] = rp[1]; r[q][2] = rp[2]; r[q][3] = rp[3];
                } else { r[q][0] = 0; r[q][1] = 0; r[q][2] = 0; r[q][3] = 0; }
            }
            // resolve greedy among the batch on the owner lane
            u32 kmask = 0;
            if (lane == owner) {
                u64 sup = r[0][sub];
                kmask = 1u;
                #pragma unroll
                for (int q = 1; q < 8; q++) {
                    if (q < m && !((sup >> b[q]) & 1ULL)) { kmask |= 1u << q; sup |= r[q][sub]; }
                }
            }
            kmask = __shfl_sync(0xffffffffu, kmask, owner);
            u64 s0 = 0, s1 = 0, s2 = 0, s3 = 0;
            #pragma unroll
            for (int q = 0; q < 8; q++) if (kmask & (1u << q)) {
                s0 |= r[q][0]; s1 |= r[q][1]; s2 |= r[q][2]; s3 |= r[q][3];
            }
            av[0] &= ~s0; av[1] &= ~s1; av[2] &= ~s2; av[3] &= ~s3;
            if (lane == owner) av[sub] &= ~examined;
            if (lane == 0) {
                int w = nk;
                #pragma unroll
                for (int q = 0; q < 8; q++)
                    if ((kmask & (1u << q)) && w < MAXDET) sKept[w++] = (lw << 6) + b[q];
            }
            nk += __popc(kmask);
        }
        if (lane == 0) sNk = nk < MAXDET ? nk : MAXDET;
    }
    __syncthreads();
    int nk = sNk;
    for (int s = t; s < MAXDET; s += 128) {
        float4 b = make_float4(0.f, 0.f, 0.f, 0.f);
        float cls = 0.f, sc = 0.f;
        if (s < nk) {
            int i = sKept[s];
            b = g_boxes[i]; cls = g_classes[i]; sc = g_scores[i];
        }
        out[s * 4 + 0] = b.x; out[s * 4 + 1] = b.y;
        out[s * 4 + 2] = b.z; out[s * 4 + 3] = b.w;
        out[MAXDET * 4 + s] = cls;
        out[MAXDET * 5 + s] = sc;
    }
}

extern "C" void kernel_launch(void* const* d_in, const int* in_sizes, int n_in,
                              void* d_out, int out_size) {
    const float* preds = (const float*)d_in[0];
    float* out = (float*)d_out;

    k_init<<<256, 256>>>();
    k_score<<<(N_ANCH + 7) / 8, 256>>>(preds);
    k_thresh<<<1, 1024>>>();
    k_place<<<(N_ANCH + 255) / 256, 256>>>();
    k_sortbins<<<CAP / 256, 256>>>(preds);
    k_mask<<<dim3(128, 128), 64>>>();
    k_scan<<<1, 128>>>(out);
}

// round 5
// speedup vs baseline: 1.0223x; 1.0223x over previous
#include <cuda_runtime.h>
#include <cstdint>

#define N_ANCH 102000
#define ROWLEN 85
#define CONF 0.25f
#define IOUT 0.45f
#define TOPK 8192
#define KW 128            // 8192/64 words per mask row
#define MAXDET 300
#define CAP 16384
#define NBIN 65536

typedef unsigned long long u64;
typedef unsigned int u32;

// ---------------- static device scratch ----------------
__device__ u64 g_keys[N_ANCH];
__device__ u32 g_cls[N_ANCH];
__device__ u32 g_hist[NBIN];
__device__ u32 g_binoff[NBIN];
__device__ u32 g_bincnt[NBIN];
__device__ int g_thrbin;
__device__ u64 g_slot[CAP];
__device__ float4 g_boxes[TOPK];
__device__ float g_scores[TOPK];
__device__ float g_classes[TOPK];
__device__ u64 g_validm[KW];
__device__ u64 g_mask[(size_t)TOPK * KW];   // 8 MB (fits in L2)

// ---------------- K0: zero per-call state ----------------
__global__ void k_init() {
    int t = blockIdx.x * blockDim.x + threadIdx.x;   // 65536 threads
    g_hist[t] = 0u;
    g_bincnt[t] = 0u;
    if (t < CAP) g_slot[t] = 0ULL;
    if (t < KW) g_validm[t] = 0ULL;
    if (t == 0) g_thrbin = 0;
}

// ---------------- K1: score/class + key + 16-bit histogram ----------------
__global__ void k_score(const float* __restrict__ preds) {
    int warp = (blockIdx.x * blockDim.x + threadIdx.x) >> 5;
    int lane = threadIdx.x & 31;
    if (warp >= N_ANCH) return;
    const float* p = preds + (size_t)warp * ROWLEN;
    float e0 = p[lane];
    float obj = __shfl_sync(0xffffffffu, e0, 4);
    u32 sb = 0; int bc = 0;
    if (obj > CONF) {
        float e1 = p[lane + 32];
        float e2 = (lane < 21) ? p[lane + 64] : 0.0f;
        float bv = -1.0f;
        if (lane >= 5) { bv = e0 * obj; bc = lane - 5; }
        float v1 = e1 * obj;
        if (v1 > bv) { bv = v1; bc = lane + 27; }
        if (lane < 21) { float v2 = e2 * obj; if (v2 > bv) { bv = v2; bc = lane + 59; } }
        u32 vb = __float_as_uint(bv);
        u32 m = __reduce_max_sync(0xffffffffu, vb);
        u32 cm = __reduce_min_sync(0xffffffffu, (vb == m) ? (u32)bc : 0xFFFFu);
        sb = m; bc = (int)cm;
    }
    if (lane == 0) {
        g_keys[warp] = ((u64)sb << 32) | (u64)(0xFFFFFFFFu - (u32)warp);
        g_cls[warp] = (u32)bc;
        if (sb) atomicAdd(&g_hist[sb >> 16], 1u);
    }
}

// ---------------- K2: threshold bin + per-bin descending exclusive offsets ----------------
__global__ void k_thresh() {
    __shared__ u32 part[1024];
    int t = threadIdx.x;
    u32 s = 0;
    #pragma unroll
    for (int b = 0; b < 64; b++) s += g_hist[t * 64 + b];
    part[t] = s;
    __syncthreads();
    for (int off = 1; off < 1024; off <<= 1) {   // inclusive suffix sum of chunks
        u32 v = part[t] + ((t + off < 1024) ? part[t + off] : 0u);
        __syncthreads();
        part[t] = v;
        __syncthreads();
    }
    u32 sufNext = (t < 1023) ? part[t + 1] : 0u;
    if (part[t] >= TOPK && sufNext < TOPK) {
        u32 acc = sufNext;
        for (int b = 63; b >= 0; b--) {
            acc += g_hist[t * 64 + b];
            if (acc >= TOPK) { g_thrbin = t * 64 + b; break; }
        }
    }
    if (t == 0 && part[0] < TOPK) g_thrbin = 0;
    u32 acc = sufNext;
    for (int b = 63; b >= 0; b--) {
        g_binoff[t * 64 + b] = acc;
        acc += g_hist[t * 64 + b];
    }
}

// ---------------- K3: place candidates into bin regions ----------------
__global__ void k_place() {
    int i = blockIdx.x * blockDim.x + threadIdx.x;
    if (i >= N_ANCH) return;
    u64 k = g_keys[i];
    u32 sb = (u32)(k >> 32);
    if (!sb) return;
    int bin = (int)(sb >> 16);
    if (bin < g_thrbin) return;
    u32 p = g_binoff[bin] + atomicAdd(&g_bincnt[bin], 1u);
    if (p < CAP) g_slot[p] = k;
}

// ---------------- K4: within-bin rank + direct gather/write ----------------
__global__ void k_sortbins(const float* __restrict__ preds) {
    int p = blockIdx.x * blockDim.x + threadIdx.x;
    if (p >= CAP) return;
    u64 k = g_slot[p];
    if (!k) return;
    int bin = (int)(k >> 48);
    u32 off = g_binoff[bin];
    u32 cnt = g_bincnt[bin];
    u32 end = off + cnt; if (end > CAP) end = CAP;
    u32 r = off;
    for (u32 q = off; q < end; q++) r += (g_slot[q] > k) ? 1u : 0u;
    if (r >= TOPK) return;
    u32 idx = 0xFFFFFFFFu - (u32)k;
    float s = __uint_as_float((u32)(k >> 32));
    const float* pr = preds + (size_t)idx * ROWLEN;
    float x = pr[0], y = pr[1], w = pr[2], h = pr[3];
    float4 b;
    b.x = y - h * 0.5f;
    b.y = x - w * 0.5f;
    b.z = y + h * 0.5f;
    b.w = x + w * 0.5f;
    g_boxes[r] = b;
    g_scores[r] = s;
    g_classes[r] = (float)g_cls[idx];
    atomicOr(&g_validm[r >> 6], 1ULL << (r & 63));
}

// ---------------- K5: full IoU bitmask (upper-triangular 64x64 tiles) ----------------
__global__ void k_mask() {
    int cy = blockIdx.y, cx = blockIdx.x;
    if (cx < cy) return;
    int t = threadIdx.x;  // 64
    __shared__ float4 sb4[64];
    __shared__ float sa[64];
    float4 jb = g_boxes[cx * 64 + t];
    sb4[t] = jb;
    sa[t] = (jb.z - jb.x) * (jb.w - jb.y);
    float4 ib = g_boxes[cy * 64 + t];
    float ai = (ib.z - ib.x) * (ib.w - ib.y);
    __syncthreads();
    u64 bits = 0;
    int jstart = (cx == cy) ? t + 1 : 0;
    for (int j = jstart; j < 64; j++) {
        float4 b2 = sb4[j];
        float ty = fmaxf(ib.x, b2.x);
        float tx = fmaxf(ib.y, b2.y);
        float by = fminf(ib.z, b2.z);
        float bx = fminf(ib.w, b2.w);
        float inter = fmaxf(by - ty, 0.0f) * fmaxf(bx - tx, 0.0f);
        float uni = ai + sa[j] - inter;
        float iou = inter / (uni + 1e-9f);
        if (iou > IOUT) bits |= (1ULL << j);
    }
    g_mask[(size_t)(cy * 64 + t) * KW + cx] = bits;
}

// select one of 4 named scalars by runtime index (SEL chain, no local memory)
#define SEL4(s, v0, v1, v2, v3) ((s) == 0 ? (v0) : (s) == 1 ? (v1) : (s) == 2 ? (v2) : (v3))

// ---------------- K6: batch-4 greedy scan (1 warp, static regs only) + output ----------------
__global__ void k_scan(float* __restrict__ out) {
    __shared__ int sKept[MAXDET];
    __shared__ int sNk;
    int t = threadIdx.x;    // 128 threads; warp 0 scans
    if (t < 32) {
        int lane = t;
        u64 a0 = g_validm[lane * 4 + 0];
        u64 a1 = g_validm[lane * 4 + 1];
        u64 a2 = g_validm[lane * 4 + 2];
        u64 a3 = g_validm[lane * 4 + 3];
        int nk = 0;
        while (nk < MAXDET) {
            // lowest nonzero word index across the 128 words
            int lw = 128;
            if (a3) lw = lane * 4 + 3;
            if (a2) lw = lane * 4 + 2;
            if (a1) lw = lane * 4 + 1;
            if (a0) lw = lane * 4 + 0;
            lw = (int)__reduce_min_sync(0xffffffffu, (u32)lw);
            if (lw == 128) break;
            int owner = lw >> 2, sub = lw & 3;
            u64 mysub = SEL4(sub, a0, a1, a2, a3);
            u64 aw = __shfl_sync(0xffffffffu, mysub, owner);
            // up to 4 lowest set bits (uniform across warp)
            int b0 = __ffsll((long long)aw) - 1;  u64 t1 = aw & (aw - 1);
            int b1 = __ffsll((long long)t1) - 1;  u64 t2 = t1 & (t1 - 1);
            int b2 = __ffsll((long long)t2) - 1;  u64 t3 = t2 & (t2 - 1);
            int b3 = __ffsll((long long)t3) - 1;  u64 t4 = t3 & (t3 - 1);
            bool h1 = (t1 != 0ULL), h2 = (t2 != 0ULL), h3 = (t3 != 0ULL);
            u64 examined = aw ^ t4;
            size_t rowb = (size_t)(lw << 6);
            const u64* m0 = &g_mask[(rowb + b0) * KW + lane * 4];
            u64 r00 = m0[0], r01 = m0[1], r02 = m0[2], r03 = m0[3];
            u64 r10 = 0, r11 = 0, r12 = 0, r13 = 0;
            u64 r20 = 0, r21 = 0, r22 = 0, r23 = 0;
            u64 r30 = 0, r31 = 0, r32 = 0, r33 = 0;
            if (h1) { const u64* m1 = &g_mask[(rowb + b1) * KW + lane * 4];
                      r10 = m1[0]; r11 = m1[1]; r12 = m1[2]; r13 = m1[3]; }
            if (h2) { const u64* m2 = &g_mask[(rowb + b2) * KW + lane * 4];
                      r20 = m2[0]; r21 = m2[1]; r22 = m2[2]; r23 = m2[3]; }
            if (h3) { const u64* m3 = &g_mask[(rowb + b3) * KW + lane * 4];
                      r30 = m3[0]; r31 = m3[1]; r32 = m3[2]; r33 = m3[3]; }
            // greedy resolve among the batch on the owner lane (word lw bits only)
            u32 kmask = 1u;
            if (lane == owner) {
                u64 sup = SEL4(sub, r00, r01, r02, r03);
                if (h1 && !((sup >> b1) & 1ULL)) { kmask |= 2u; sup |= SEL4(sub, r10, r11, r12, r13); }
                if (h2 && !((sup >> b2) & 1ULL)) { kmask |= 4u; sup |= SEL4(sub, r20, r21, r22, r23); }
                if (h3 && !((sup >> b3) & 1ULL)) { kmask |= 8u; }
            }
            kmask = __shfl_sync(0xffffffffu, kmask, owner);
            u64 s0 = r00, s1 = r01, s2 = r02, s3 = r03;
            if (kmask & 2u) { s0 |= r10; s1 |= r11; s2 |= r12; s3 |= r13; }
            if (kmask & 4u) { s0 |= r20; s1 |= r21; s2 |= r22; s3 |= r23; }
            if (kmask & 8u) { s0 |= r30; s1 |= r31; s2 |= r32; s3 |= r33; }
            a0 &= ~s0; a1 &= ~s1; a2 &= ~s2; a3 &= ~s3;
            if (lane == owner) {
                if (sub == 0) a0 &= ~examined;
                else if (sub == 1) a1 &= ~examined;
                else if (sub == 2) a2 &= ~examined;
                else a3 &= ~examined;
            }
            if (lane == 0) {
                int w = nk;
                if (w < MAXDET) sKept[w++] = (lw << 6) + b0;
                if ((kmask & 2u) && w < MAXDET) sKept[w++] = (lw << 6) + b1;
                if ((kmask & 4u) && w < MAXDET) sKept[w++] = (lw << 6) + b2;
                if ((kmask & 8u) && w < MAXDET) sKept[w++] = (lw << 6) + b3;
            }
            nk += __popc(kmask);
        }
        if (lane == 0) sNk = nk < MAXDET ? nk : MAXDET;
    }
    __syncthreads();
    int nk = sNk;
    for (int s = t; s < MAXDET; s += 128) {
        float4 b = make_float4(0.f, 0.f, 0.f, 0.f);
        float cls = 0.f, sc = 0.f;
        if (s < nk) {
            int i = sKept[s];
            b = g_boxes[i]; cls = g_classes[i]; sc = g_scores[i];
        }
        out[s * 4 + 0] = b.x; out[s * 4 + 1] = b.y;
        out[s * 4 + 2] = b.z; out[s * 4 + 3] = b.w;
        out[MAXDET * 4 + s] = cls;
        out[MAXDET * 5 + s] = sc;
    }
}

extern "C" void kernel_launch(void* const* d_in, const int* in_sizes, int n_in,
                              void* d_out, int out_size) {
    const float* preds = (const float*)d_in[0];
    float* out = (float*)d_out;

    k_init<<<256, 256>>>();
    k_score<<<(N_ANCH + 7) / 8, 256>>>(preds);
    k_thresh<<<1, 1024>>>();
    k_place<<<(N_ANCH + 255) / 256, 256>>>();
    k_sortbins<<<CAP / 256, 256>>>(preds);
    k_mask<<<dim3(128, 128), 64>>>();
    k_scan<<<1, 128>>>(out);
}